// round 8
// baseline (speedup 1.0000x reference)
#include <cuda_runtime.h>
#include <cuda_bf16.h>
#include <math.h>
#include <stdint.h>

// Problem constants
#define Bb 2
#define Nn 4096
#define Mm 32
#define Cc 256
#define Hh 8
#define T2 625
#define SCALE 0.17677669529663687f   // 32^-0.5
#define ROWS (Bb*Nn)                  // 8192

// attn smem: K tile 32 rows x 260 floats + q 256 floats
#define KP 260
#define ATTN_SMEM ((32*KP + 256) * 4) // 34304 bytes

// GEMM pipeline config
#define STAGES 4
#define APITCH 20
#define BPITCH 136
#define A_TILE (128*APITCH)
#define B_TILE (16*BPITCH)
#define STAGE_FLOATS (A_TILE + B_TILE)
#define GEMM_SMEM (STAGES*STAGE_FLOATS*4) // 75776 bytes

// Scratch
__device__ float g_qkv[(size_t)ROWS * 768];      // [q(256) | per-head (k32,v32) x8]
__device__ float g_attnout[(size_t)ROWS * Cc];
__device__ float g_pe[T2 * Hh];
__device__ int   g_mask_is_u8;

// ---------------------------------------------------------------------------
__global__ void detect_mask_kernel(const unsigned int* __restrict__ m)
{
    int found = 0;
#pragma unroll
    for (int j = 0; j < 8; j++) {
        if (m[threadIdx.x + j * 256] > 1u) found = 1;
    }
    int any = __syncthreads_or(found);
    if (threadIdx.x == 0) g_mask_is_u8 = any;
}

// ---------------------------------------------------------------------------
__global__ void pe_kernel(const float* __restrict__ pre_table,
                          const float* __restrict__ W_pe,
                          const float* __restrict__ b_pe)
{
    int i = blockIdx.x * blockDim.x + threadIdx.x;
    if (i >= T2 * Hh) return;
    int t = i >> 3;
    int h = i & 7;
    float acc = b_pe[h];
#pragma unroll
    for (int j = 0; j < 5; j++)
        acc += pre_table[t * 5 + j] * W_pe[j * Hh + h];
    g_pe[i] = acc;
}

// ---------------------------------------------------------------------------
__device__ __forceinline__ uint32_t f2tf32(float f)
{
    uint32_t r;
    asm("cvt.rna.tf32.f32 %0, %1;" : "=r"(r) : "f"(f));
    return r;
}

__device__ __forceinline__ void mma_tf32(float* d, const uint32_t* a, const uint32_t* b)
{
    asm volatile(
        "mma.sync.aligned.m16n8k8.row.col.f32.tf32.tf32.f32 "
        "{%0,%1,%2,%3}, {%4,%5,%6,%7}, {%8,%9}, {%0,%1,%2,%3};"
        : "+f"(d[0]), "+f"(d[1]), "+f"(d[2]), "+f"(d[3])
        : "r"(a[0]), "r"(a[1]), "r"(a[2]), "r"(a[3]), "r"(b[0]), "r"(b[1]));
}

__device__ __forceinline__ uint32_t smem_u32(const void* p)
{
    uint32_t r;
    asm("{ .reg .u64 t; cvta.to.shared.u64 t, %1; cvt.u32.u64 %0, t; }"
        : "=r"(r) : "l"(p));
    return r;
}

__device__ __forceinline__ void cp16(uint32_t dst, const void* src)
{
    asm volatile("cp.async.ca.shared.global [%0], [%1], 16;"
                 :: "r"(dst), "l"(src));
}

// ---------------------------------------------------------------------------
// Shared tf32 GEMM body (BM=BN=128, BK=16, 4-stage cp.async pipeline).
// ---------------------------------------------------------------------------
__device__ __forceinline__ void gemm_body(
    const float* __restrict__ A, const float* __restrict__ W,
    const float* __restrict__ bias, float* __restrict__ Cout,
    int K, int Ncols, int ldout, int block_m, int wcol, int outcol,
    float* sm)
{
    const int tid = threadIdx.x;
    const int wid = tid >> 5;
    const int lane = tid & 31;
    const int wm = (wid & 3) * 32;
    const int wn = (wid >> 2) * 64;
    const int lr = lane >> 2;
    const int lc = lane & 3;

    const int arow = tid >> 1;
    const int acol = (tid & 1) * 8;
    const int brow = tid >> 4;
    const int bcol = (tid & 15) * 8;

    const float* Aptr = A + (size_t)(block_m + arow) * K + acol;
    const float* Wptr = W + (size_t)brow * Ncols + wcol + bcol;

    float acc[2][8][4];
#pragma unroll
    for (int i = 0; i < 2; i++)
#pragma unroll
        for (int j = 0; j < 8; j++)
#pragma unroll
            for (int t = 0; t < 4; t++) acc[i][j][t] = 0.f;

    const int NIT = K >> 4;

    auto issue_tile = [&](int s, int k0) {
        float* as = sm + s * STAGE_FLOATS;
        float* bs = as + A_TILE;
        uint32_t ad = smem_u32(as + arow * APITCH + acol);
        const char* asrc = (const char*)(Aptr + k0);
        cp16(ad, asrc);
        cp16(ad + 16, asrc + 16);
        uint32_t bd = smem_u32(bs + brow * BPITCH + bcol);
        const char* bsrc = (const char*)(Wptr + (size_t)k0 * Ncols);
        cp16(bd, bsrc);
        cp16(bd + 16, bsrc + 16);
    };

#pragma unroll
    for (int s = 0; s < STAGES - 1; s++) {
        if (s < NIT) issue_tile(s, s * 16);
        asm volatile("cp.async.commit_group;");
    }

    for (int it = 0; it < NIT; it++) {
        asm volatile("cp.async.wait_group %0;" :: "n"(STAGES - 2));
        __syncthreads();
        if (it + STAGES - 1 < NIT)
            issue_tile((it + STAGES - 1) % STAGES, (it + STAGES - 1) * 16);
        asm volatile("cp.async.commit_group;");

        const float* as = sm + (it % STAGES) * STAGE_FLOATS;
        const float* bs = as + A_TILE;
#pragma unroll
        for (int kk = 0; kk < 16; kk += 8) {
            uint32_t afr[2][4], bfr[8][2];
#pragma unroll
            for (int mf = 0; mf < 2; mf++) {
                const int r = wm + mf * 16 + lr;
                afr[mf][0] = f2tf32(as[r * APITCH + kk + lc]);
                afr[mf][1] = f2tf32(as[(r + 8) * APITCH + kk + lc]);
                afr[mf][2] = f2tf32(as[r * APITCH + kk + lc + 4]);
                afr[mf][3] = f2tf32(as[(r + 8) * APITCH + kk + lc + 4]);
            }
#pragma unroll
            for (int nf = 0; nf < 8; nf++) {
                const int cn = wn + nf * 8 + lr;
                bfr[nf][0] = f2tf32(bs[(kk + lc) * BPITCH + cn]);
                bfr[nf][1] = f2tf32(bs[(kk + lc + 4) * BPITCH + cn]);
            }
#pragma unroll
            for (int mf = 0; mf < 2; mf++)
#pragma unroll
                for (int nf = 0; nf < 8; nf++)
                    mma_tf32(acc[mf][nf], afr[mf], bfr[nf]);
        }
    }

#pragma unroll
    for (int mf = 0; mf < 2; mf++) {
        const int row0 = block_m + wm + mf * 16 + lr;
#pragma unroll
        for (int nf = 0; nf < 8; nf++) {
            const int cl = wn + nf * 8 + lc * 2;
            float2 bv = *(const float2*)(bias + wcol + cl);
            float2 v0 = make_float2(acc[mf][nf][0] + bv.x, acc[mf][nf][1] + bv.y);
            float2 v1 = make_float2(acc[mf][nf][2] + bv.x, acc[mf][nf][3] + bv.y);
            *(float2*)(Cout + (size_t)row0 * ldout + outcol + cl) = v0;
            *(float2*)(Cout + (size_t)(row0 + 8) * ldout + outcol + cl) = v1;
        }
    }
}

// Fused Q+KV projection: grid (6, 64).
__global__ __launch_bounds__(256, 2) void qkv_gemm_kernel(
    const float* __restrict__ A,
    const float* __restrict__ Wq, const float* __restrict__ bq,
    const float* __restrict__ Wkv, const float* __restrict__ bkv,
    float* __restrict__ qkv)
{
    extern __shared__ float sm[];
    const int bx = blockIdx.x;
    const float *W, *bias;
    int Ncols, wcol, outcol;
    if (bx < 2) { W = Wq;  bias = bq;  Ncols = 256; wcol = bx * 128;       outcol = wcol; }
    else        { W = Wkv; bias = bkv; Ncols = 512; wcol = (bx - 2) * 128; outcol = 256 + wcol; }
    gemm_body(A, W, bias, qkv, 256, Ncols, 768, blockIdx.y * 128, wcol, outcol, sm);
}

// Output projection: grid (2, 64).
__global__ __launch_bounds__(256, 2) void proj_gemm_kernel(
    const float* __restrict__ A,
    const float* __restrict__ W, const float* __restrict__ bias,
    float* __restrict__ out)
{
    extern __shared__ float sm[];
    gemm_body(A, W, bias, out, 256, 256, 256,
              blockIdx.y * 128, blockIdx.x * 128, blockIdx.x * 128, sm);
}

// ---------------------------------------------------------------------------
// Fused gather + scores + softmax + weighted-V.
// K staged in smem; V prefetched into registers (2 batches of 16) so its
// L2 latency overlaps score compute + softmax.
// ---------------------------------------------------------------------------
__global__ __launch_bounds__(256) void attn_kernel(
    const int* __restrict__ member_idx,
    const void* __restrict__ cluster_mask,
    const int* __restrict__ pe_idx,
    const float* __restrict__ blank_k,
    const float* __restrict__ blank_v)
{
    extern __shared__ float smem[];
    float* kv  = smem;            // 32 rows x KP (K only)
    float* qsh = smem + 32 * KP;  // 256

    const int bn   = blockIdx.x;
    const int tid  = threadIdx.x;
    const int h    = tid >> 5;
    const int lane = tid & 31;
    const int b    = bn >> 12;     // N = 4096

    // ---- phase 1: stage q + gathered K (cp.async) ----
    const int mbase = bn * Mm;
    const int mrow = tid >> 3;
    const int sub  = tid & 7;
    const int gidx = __ldg(member_idx + mbase + mrow);
    const char* src = (const char*)(g_qkv + ((size_t)(b * Nn + gidx)) * 768 + 256);

    uint32_t dst_base = smem_u32(kv + mrow * KP);
#pragma unroll
    for (int j = 0; j < 8; j++) {
        cp16(dst_base + j * 128 + sub * 16, src + j * 256 + sub * 16);
    }
    asm volatile("cp.async.commit_group;");

    qsh[tid] = g_qkv[(size_t)bn * 768 + tid];

    // per-lane member metadata (lane = member m)
    const int   gidx_l = __ldg(member_idx + mbase + lane);
    const int   pid    = pe_idx[mbase + lane];
    bool msk;
    if (g_mask_is_u8)
        msk = ((const unsigned char*)cluster_mask)[mbase + lane] != 0;
    else
        msk = ((const int*)cluster_mask)[mbase + lane] != 0;

    // ---- V prefetch batch 1 (m = 0..15): overlaps K staging + scores ----
    const float* vb = g_qkv + (size_t)b * Nn * 768 + 256 + h * 64 + 32 + lane;
    float vreg[16];
#pragma unroll
    for (int m = 0; m < 16; m++) {
        int r = __shfl_sync(0xFFFFFFFFu, gidx_l, m);
        vreg[m] = __ldg(vb + (size_t)r * 768);
    }

    asm volatile("cp.async.wait_group 0;");
    __syncthreads();

    // ---- phase 2: score + softmax (lane = member m) ----
    const float* qh = qsh + h * 32;
    const float4* krow4 = (const float4*)(kv + lane * KP + h * 32);
    float score = 0.f;
#pragma unroll
    for (int i = 0; i < 8; i++) {
        float4 kk = krow4[i];
        score = fmaf(kk.x, qh[4*i+0], score);
        score = fmaf(kk.y, qh[4*i+1], score);
        score = fmaf(kk.z, qh[4*i+2], score);
        score = fmaf(kk.w, qh[4*i+3], score);
    }
    score = score * SCALE + g_pe[pid * Hh + h];
    if (!msk) score = -3.0e38f;

    float bsp = qh[lane] * blank_k[h * 32 + lane];
#pragma unroll
    for (int o = 16; o > 0; o >>= 1)
        bsp += __shfl_xor_sync(0xFFFFFFFFu, bsp, o);
    const float bs = bsp * SCALE;

    float mx = score;
#pragma unroll
    for (int o = 16; o > 0; o >>= 1)
        mx = fmaxf(mx, __shfl_xor_sync(0xFFFFFFFFu, mx, o));
    mx = fmaxf(mx, bs);

    float p  = __expf(score - mx);
    float pb = __expf(bs - mx);
    float s = p;
#pragma unroll
    for (int o = 16; o > 0; o >>= 1)
        s += __shfl_xor_sync(0xFFFFFFFFu, s, o);
    s += pb;
    const float inv = 1.f / s;
    const float a  = p * inv;
    const float ab = pb * inv;

    // ---- V prefetch batch 2 (m = 16..31): issue before consuming batch 1 ----
    float vreg2[16];
#pragma unroll
    for (int m = 0; m < 16; m++) {
        int r = __shfl_sync(0xFFFFFFFFu, gidx_l, m + 16);
        vreg2[m] = __ldg(vb + (size_t)r * 768);
    }

    // ---- phase 3: weighted V sum (lane = channel c) ----
    float out = ab * blank_v[h * 32 + lane];
    float out2 = 0.f;
#pragma unroll
    for (int m = 0; m < 16; m++) {
        float w = __shfl_sync(0xFFFFFFFFu, a, m);
        if (m & 1) out2 = fmaf(w, vreg[m], out2);
        else       out  = fmaf(w, vreg[m], out);
    }
#pragma unroll
    for (int m = 0; m < 16; m++) {
        float w = __shfl_sync(0xFFFFFFFFu, a, m + 16);
        if (m & 1) out2 = fmaf(w, vreg2[m], out2);
        else       out  = fmaf(w, vreg2[m], out);
    }
    out += out2;

    g_attnout[(size_t)bn * Cc + h * 32 + lane] = out;
}

// ---------------------------------------------------------------------------
extern "C" void kernel_launch(void* const* d_in, const int* in_sizes, int n_in,
                              void* d_out, int out_size)
{
    const float* feat   = (const float*)d_in[0];
    const int*   member = (const int*)d_in[1];
    const void*  mask   = d_in[2];
    const int*   peidx  = (const int*)d_in[3];

    int p = 4;
    for (int i = 4; i < n_in; i++) {
        if (in_sizes[i] == 3125) { p = i; break; }
    }
    const float* pre_table = (const float*)d_in[p];
    const float* Wq        = (const float*)d_in[p + 1];
    const float* bq        = (const float*)d_in[p + 2];
    const float* Wkv       = (const float*)d_in[p + 3];
    const float* bkv       = (const float*)d_in[p + 4];
    const float* W_pe      = (const float*)d_in[p + 5];
    const float* b_pe      = (const float*)d_in[p + 6];
    const float* blank_k   = (const float*)d_in[p + 7];
    const float* blank_v   = (const float*)d_in[p + 8];
    const float* Wproj     = (const float*)d_in[p + 9];
    const float* bproj     = (const float*)d_in[p + 10];
    float* out = (float*)d_out;

    float* qkv = nullptr;
    float* attnout = nullptr;
    cudaGetSymbolAddress((void**)&qkv, g_qkv);
    cudaGetSymbolAddress((void**)&attnout, g_attnout);

    cudaFuncSetAttribute(attn_kernel,
                         cudaFuncAttributeMaxDynamicSharedMemorySize, ATTN_SMEM);
    cudaFuncSetAttribute(qkv_gemm_kernel,
                         cudaFuncAttributeMaxDynamicSharedMemorySize, GEMM_SMEM);
    cudaFuncSetAttribute(proj_gemm_kernel,
                         cudaFuncAttributeMaxDynamicSharedMemorySize, GEMM_SMEM);

    detect_mask_kernel<<<1, 256>>>((const unsigned int*)mask);
    pe_kernel<<<(T2 * Hh + 255) / 256, 256>>>(pre_table, W_pe, b_pe);

    {   // fused Q+KV projection
        dim3 grid(6, ROWS / 128);
        qkv_gemm_kernel<<<grid, 256, GEMM_SMEM>>>(feat, Wq, bq, Wkv, bkv, qkv);
    }

    attn_kernel<<<ROWS, 256, ATTN_SMEM>>>(member, mask, peidx, blank_k, blank_v);

    {   // output projection
        dim3 grid(2, ROWS / 128);
        proj_gemm_kernel<<<grid, 256, GEMM_SMEM>>>(attnout, Wproj, bproj, out);
    }
}

// round 9
// speedup vs baseline: 1.0361x; 1.0361x over previous
#include <cuda_runtime.h>
#include <cuda_bf16.h>
#include <math.h>
#include <stdint.h>

// Problem constants
#define Bb 2
#define Nn 4096
#define Mm 32
#define Cc 256
#define Hh 8
#define T2 625
#define SCALE 0.17677669529663687f   // 32^-0.5
#define ROWS (Bb*Nn)                  // 8192

// attn smem: K tile 32 rows x 260 floats + q 256 floats
#define KP 260
#define ATTN_SMEM ((32*KP + 256) * 4) // 34304 bytes

// GEMM pipeline config
#define STAGES 4
#define APITCH 20
#define BPITCH 136
#define A_TILE (128*APITCH)
#define B_TILE (16*BPITCH)
#define STAGE_FLOATS (A_TILE + B_TILE)
#define GEMM_SMEM (STAGES*STAGE_FLOATS*4) // 75776 bytes

// Scratch
__device__ float g_qkv[(size_t)ROWS * 768];      // [q(256) | per-head (k32,v32) x8]
__device__ float g_attnout[(size_t)ROWS * Cc];
__device__ float g_pe[T2 * Hh];
__device__ int   g_mask_is_u8;

// ---------------------------------------------------------------------------
__global__ void detect_mask_kernel(const unsigned int* __restrict__ m)
{
    int found = 0;
#pragma unroll
    for (int j = 0; j < 8; j++) {
        if (m[threadIdx.x + j * 256] > 1u) found = 1;
    }
    int any = __syncthreads_or(found);
    if (threadIdx.x == 0) g_mask_is_u8 = any;
}

// ---------------------------------------------------------------------------
__global__ void pe_kernel(const float* __restrict__ pre_table,
                          const float* __restrict__ W_pe,
                          const float* __restrict__ b_pe)
{
    int i = blockIdx.x * blockDim.x + threadIdx.x;
    if (i >= T2 * Hh) return;
    int t = i >> 3;
    int h = i & 7;
    float acc = b_pe[h];
#pragma unroll
    for (int j = 0; j < 5; j++)
        acc += pre_table[t * 5 + j] * W_pe[j * Hh + h];
    g_pe[i] = acc;
}

// ---------------------------------------------------------------------------
__device__ __forceinline__ uint32_t f2tf32(float f)
{
    uint32_t r;
    asm("cvt.rna.tf32.f32 %0, %1;" : "=r"(r) : "f"(f));
    return r;
}

__device__ __forceinline__ void mma_tf32(float* d, const uint32_t* a, const uint32_t* b)
{
    asm volatile(
        "mma.sync.aligned.m16n8k8.row.col.f32.tf32.tf32.f32 "
        "{%0,%1,%2,%3}, {%4,%5,%6,%7}, {%8,%9}, {%0,%1,%2,%3};"
        : "+f"(d[0]), "+f"(d[1]), "+f"(d[2]), "+f"(d[3])
        : "r"(a[0]), "r"(a[1]), "r"(a[2]), "r"(a[3]), "r"(b[0]), "r"(b[1]));
}

__device__ __forceinline__ uint32_t smem_u32(const void* p)
{
    uint32_t r;
    asm("{ .reg .u64 t; cvta.to.shared.u64 t, %1; cvt.u32.u64 %0, t; }"
        : "=r"(r) : "l"(p));
    return r;
}

__device__ __forceinline__ void cp16(uint32_t dst, const void* src)
{
    asm volatile("cp.async.ca.shared.global [%0], [%1], 16;"
                 :: "r"(dst), "l"(src));
}

// ---------------------------------------------------------------------------
// Shared tf32 GEMM body (BM=BN=128, BK=16, 4-stage cp.async pipeline).
// ---------------------------------------------------------------------------
__device__ __forceinline__ void gemm_body(
    const float* __restrict__ A, const float* __restrict__ W,
    const float* __restrict__ bias, float* __restrict__ Cout,
    int K, int Ncols, int ldout, int block_m, int wcol, int outcol,
    float* sm)
{
    const int tid = threadIdx.x;
    const int wid = tid >> 5;
    const int lane = tid & 31;
    const int wm = (wid & 3) * 32;
    const int wn = (wid >> 2) * 64;
    const int lr = lane >> 2;
    const int lc = lane & 3;

    const int arow = tid >> 1;
    const int acol = (tid & 1) * 8;
    const int brow = tid >> 4;
    const int bcol = (tid & 15) * 8;

    const float* Aptr = A + (size_t)(block_m + arow) * K + acol;
    const float* Wptr = W + (size_t)brow * Ncols + wcol + bcol;

    float acc[2][8][4];
#pragma unroll
    for (int i = 0; i < 2; i++)
#pragma unroll
        for (int j = 0; j < 8; j++)
#pragma unroll
            for (int t = 0; t < 4; t++) acc[i][j][t] = 0.f;

    const int NIT = K >> 4;

    auto issue_tile = [&](int s, int k0) {
        float* as = sm + s * STAGE_FLOATS;
        float* bs = as + A_TILE;
        uint32_t ad = smem_u32(as + arow * APITCH + acol);
        const char* asrc = (const char*)(Aptr + k0);
        cp16(ad, asrc);
        cp16(ad + 16, asrc + 16);
        uint32_t bd = smem_u32(bs + brow * BPITCH + bcol);
        const char* bsrc = (const char*)(Wptr + (size_t)k0 * Ncols);
        cp16(bd, bsrc);
        cp16(bd + 16, bsrc + 16);
    };

#pragma unroll
    for (int s = 0; s < STAGES - 1; s++) {
        if (s < NIT) issue_tile(s, s * 16);
        asm volatile("cp.async.commit_group;");
    }

    for (int it = 0; it < NIT; it++) {
        asm volatile("cp.async.wait_group %0;" :: "n"(STAGES - 2));
        __syncthreads();
        if (it + STAGES - 1 < NIT)
            issue_tile((it + STAGES - 1) % STAGES, (it + STAGES - 1) * 16);
        asm volatile("cp.async.commit_group;");

        const float* as = sm + (it % STAGES) * STAGE_FLOATS;
        const float* bs = as + A_TILE;
#pragma unroll
        for (int kk = 0; kk < 16; kk += 8) {
            uint32_t afr[2][4], bfr[8][2];
#pragma unroll
            for (int mf = 0; mf < 2; mf++) {
                const int r = wm + mf * 16 + lr;
                afr[mf][0] = f2tf32(as[r * APITCH + kk + lc]);
                afr[mf][1] = f2tf32(as[(r + 8) * APITCH + kk + lc]);
                afr[mf][2] = f2tf32(as[r * APITCH + kk + lc + 4]);
                afr[mf][3] = f2tf32(as[(r + 8) * APITCH + kk + lc + 4]);
            }
#pragma unroll
            for (int nf = 0; nf < 8; nf++) {
                const int cn = wn + nf * 8 + lr;
                bfr[nf][0] = f2tf32(bs[(kk + lc) * BPITCH + cn]);
                bfr[nf][1] = f2tf32(bs[(kk + lc + 4) * BPITCH + cn]);
            }
#pragma unroll
            for (int mf = 0; mf < 2; mf++)
#pragma unroll
                for (int nf = 0; nf < 8; nf++)
                    mma_tf32(acc[mf][nf], afr[mf], bfr[nf]);
        }
    }

#pragma unroll
    for (int mf = 0; mf < 2; mf++) {
        const int row0 = block_m + wm + mf * 16 + lr;
#pragma unroll
        for (int nf = 0; nf < 8; nf++) {
            const int cl = wn + nf * 8 + lc * 2;
            float2 bv = *(const float2*)(bias + wcol + cl);
            float2 v0 = make_float2(acc[mf][nf][0] + bv.x, acc[mf][nf][1] + bv.y);
            float2 v1 = make_float2(acc[mf][nf][2] + bv.x, acc[mf][nf][3] + bv.y);
            *(float2*)(Cout + (size_t)row0 * ldout + outcol + cl) = v0;
            *(float2*)(Cout + (size_t)(row0 + 8) * ldout + outcol + cl) = v1;
        }
    }
}

// Fused Q+KV projection: grid (6, 64).
__global__ __launch_bounds__(256, 2) void qkv_gemm_kernel(
    const float* __restrict__ A,
    const float* __restrict__ Wq, const float* __restrict__ bq,
    const float* __restrict__ Wkv, const float* __restrict__ bkv,
    float* __restrict__ qkv)
{
    extern __shared__ float sm[];
    const int bx = blockIdx.x;
    const float *W, *bias;
    int Ncols, wcol, outcol;
    if (bx < 2) { W = Wq;  bias = bq;  Ncols = 256; wcol = bx * 128;       outcol = wcol; }
    else        { W = Wkv; bias = bkv; Ncols = 512; wcol = (bx - 2) * 128; outcol = 256 + wcol; }
    gemm_body(A, W, bias, qkv, 256, Ncols, 768, blockIdx.y * 128, wcol, outcol, sm);
}

// Output projection: grid (2, 64).
__global__ __launch_bounds__(256, 2) void proj_gemm_kernel(
    const float* __restrict__ A,
    const float* __restrict__ W, const float* __restrict__ bias,
    float* __restrict__ out)
{
    extern __shared__ float sm[];
    gemm_body(A, W, bias, out, 256, 256, 256,
              blockIdx.y * 128, blockIdx.x * 128, blockIdx.x * 128, sm);
}

// ---------------------------------------------------------------------------
// Fused gather + scores + softmax + weighted-V.
// Mask-predicated gather: ~50% of members are masked; skip their K staging
// and V loads entirely (their softmax weight is exactly 0).
// ---------------------------------------------------------------------------
__device__ __forceinline__ bool read_mask(const void* cm, int idx, int is_u8)
{
    if (is_u8) return ((const unsigned char*)cm)[idx] != 0;
    return ((const int*)cm)[idx] != 0;
}

__global__ __launch_bounds__(256) void attn_kernel(
    const int* __restrict__ member_idx,
    const void* __restrict__ cluster_mask,
    const int* __restrict__ pe_idx,
    const float* __restrict__ blank_k,
    const float* __restrict__ blank_v)
{
    extern __shared__ float smem[];
    float* kv  = smem;            // 32 rows x KP (K only)
    float* qsh = smem + 32 * KP;  // 256

    const int bn   = blockIdx.x;
    const int tid  = threadIdx.x;
    const int h    = tid >> 5;
    const int lane = tid & 31;
    const int b    = bn >> 12;     // N = 4096
    const int is_u8 = g_mask_is_u8;

    // ---- phase 1: stage q + gathered K (cp.async), mask-predicated ----
    const int mbase = bn * Mm;
    const int mrow = tid >> 3;
    const int sub  = tid & 7;
    const bool msk_stage = read_mask(cluster_mask, mbase + mrow, is_u8);

    if (msk_stage) {
        const int gidx = __ldg(member_idx + mbase + mrow);
        const char* src = (const char*)(g_qkv + ((size_t)(b * Nn + gidx)) * 768 + 256);
        uint32_t dst_base = smem_u32(kv + mrow * KP);
#pragma unroll
        for (int j = 0; j < 8; j++) {
            cp16(dst_base + j * 128 + sub * 16, src + j * 256 + sub * 16);
        }
    }
    asm volatile("cp.async.commit_group;");

    qsh[tid] = g_qkv[(size_t)bn * 768 + tid];

    // per-lane member metadata (lane = member m)
    const int  gidx_l = __ldg(member_idx + mbase + lane);
    const bool msk    = read_mask(cluster_mask, mbase + lane, is_u8);
    const int  pid    = pe_idx[mbase + lane];
    const unsigned wmask = __ballot_sync(0xFFFFFFFFu, msk);

    // ---- V prefetch batch 1 (m = 0..15), mask-predicated ----
    const float* vb = g_qkv + (size_t)b * Nn * 768 + 256 + h * 64 + 32 + lane;
    float vreg[16];
#pragma unroll
    for (int m = 0; m < 16; m++) {
        int r = __shfl_sync(0xFFFFFFFFu, gidx_l, m);
        float v = 0.f;
        if ((wmask >> m) & 1u) v = __ldg(vb + (size_t)r * 768);
        vreg[m] = v;
    }

    asm volatile("cp.async.wait_group 0;");
    __syncthreads();

    // ---- phase 2: score + softmax (lane = member m) ----
    const float* qh = qsh + h * 32;
    const float4* krow4 = (const float4*)(kv + lane * KP + h * 32);
    float score = 0.f;
#pragma unroll
    for (int i = 0; i < 8; i++) {
        float4 kk = krow4[i];
        score = fmaf(kk.x, qh[4*i+0], score);
        score = fmaf(kk.y, qh[4*i+1], score);
        score = fmaf(kk.z, qh[4*i+2], score);
        score = fmaf(kk.w, qh[4*i+3], score);
    }
    score = score * SCALE + g_pe[pid * Hh + h];
    if (!msk) score = -3.0e38f;   // overwrites any garbage/NaN from unstaged K

    float bsp = qh[lane] * blank_k[h * 32 + lane];
#pragma unroll
    for (int o = 16; o > 0; o >>= 1)
        bsp += __shfl_xor_sync(0xFFFFFFFFu, bsp, o);
    const float bs = bsp * SCALE;

    float mx = score;
#pragma unroll
    for (int o = 16; o > 0; o >>= 1)
        mx = fmaxf(mx, __shfl_xor_sync(0xFFFFFFFFu, mx, o));
    mx = fmaxf(mx, bs);

    float p  = __expf(score - mx);
    float pb = __expf(bs - mx);
    float s = p;
#pragma unroll
    for (int o = 16; o > 0; o >>= 1)
        s += __shfl_xor_sync(0xFFFFFFFFu, s, o);
    s += pb;
    const float inv = 1.f / s;
    const float a  = p * inv;
    const float ab = pb * inv;

    // ---- V prefetch batch 2 (m = 16..31), mask-predicated ----
    float vreg2[16];
#pragma unroll
    for (int m = 0; m < 16; m++) {
        int r = __shfl_sync(0xFFFFFFFFu, gidx_l, m + 16);
        float v = 0.f;
        if ((wmask >> (m + 16)) & 1u) v = __ldg(vb + (size_t)r * 768);
        vreg2[m] = v;
    }

    // ---- phase 3: weighted V sum (lane = channel c) ----
    float out = ab * blank_v[h * 32 + lane];
    float out2 = 0.f;
#pragma unroll
    for (int m = 0; m < 16; m++) {
        float w = __shfl_sync(0xFFFFFFFFu, a, m);
        if (m & 1) out2 = fmaf(w, vreg[m], out2);
        else       out  = fmaf(w, vreg[m], out);
    }
#pragma unroll
    for (int m = 0; m < 16; m++) {
        float w = __shfl_sync(0xFFFFFFFFu, a, m + 16);
        if (m & 1) out2 = fmaf(w, vreg2[m], out2);
        else       out  = fmaf(w, vreg2[m], out);
    }
    out += out2;

    g_attnout[(size_t)bn * Cc + h * 32 + lane] = out;
}

// ---------------------------------------------------------------------------
extern "C" void kernel_launch(void* const* d_in, const int* in_sizes, int n_in,
                              void* d_out, int out_size)
{
    const float* feat   = (const float*)d_in[0];
    const int*   member = (const int*)d_in[1];
    const void*  mask   = d_in[2];
    const int*   peidx  = (const int*)d_in[3];

    int p = 4;
    for (int i = 4; i < n_in; i++) {
        if (in_sizes[i] == 3125) { p = i; break; }
    }
    const float* pre_table = (const float*)d_in[p];
    const float* Wq        = (const float*)d_in[p + 1];
    const float* bq        = (const float*)d_in[p + 2];
    const float* Wkv       = (const float*)d_in[p + 3];
    const float* bkv       = (const float*)d_in[p + 4];
    const float* W_pe      = (const float*)d_in[p + 5];
    const float* b_pe      = (const float*)d_in[p + 6];
    const float* blank_k   = (const float*)d_in[p + 7];
    const float* blank_v   = (const float*)d_in[p + 8];
    const float* Wproj     = (const float*)d_in[p + 9];
    const float* bproj     = (const float*)d_in[p + 10];
    float* out = (float*)d_out;

    float* qkv = nullptr;
    float* attnout = nullptr;
    cudaGetSymbolAddress((void**)&qkv, g_qkv);
    cudaGetSymbolAddress((void**)&attnout, g_attnout);

    cudaFuncSetAttribute(attn_kernel,
                         cudaFuncAttributeMaxDynamicSharedMemorySize, ATTN_SMEM);
    cudaFuncSetAttribute(qkv_gemm_kernel,
                         cudaFuncAttributeMaxDynamicSharedMemorySize, GEMM_SMEM);
    cudaFuncSetAttribute(proj_gemm_kernel,
                         cudaFuncAttributeMaxDynamicSharedMemorySize, GEMM_SMEM);

    detect_mask_kernel<<<1, 256>>>((const unsigned int*)mask);
    pe_kernel<<<(T2 * Hh + 255) / 256, 256>>>(pre_table, W_pe, b_pe);

    {   // fused Q+KV projection
        dim3 grid(6, ROWS / 128);
        qkv_gemm_kernel<<<grid, 256, GEMM_SMEM>>>(feat, Wq, bq, Wkv, bkv, qkv);
    }

    attn_kernel<<<ROWS, 256, ATTN_SMEM>>>(member, mask, peidx, blank_k, blank_v);

    {   // output projection
        dim3 grid(2, ROWS / 128);
        proj_gemm_kernel<<<grid, 256, GEMM_SMEM>>>(attnout, Wproj, bproj, out);
    }
}

// round 10
// speedup vs baseline: 1.0929x; 1.0548x over previous
#include <cuda_runtime.h>
#include <cuda_bf16.h>
#include <math.h>
#include <stdint.h>

// Problem constants
#define Bb 2
#define Nn 4096
#define Mm 32
#define Cc 256
#define Hh 8
#define T2 625
#define SCALE 0.17677669529663687f   // 32^-0.5
#define ROWS (Bb*Nn)                  // 8192

// attn smem: K tile 32x260 + q 256 + weights 256 + voff 32
#define KP 260
#define ATTN_SMEM ((32*KP + 256 + 256 + 32) * 4) // 35456 bytes

// GEMM pipeline config
#define STAGES 4
#define APITCH 20
#define BPITCH 136
#define A_TILE (128*APITCH)
#define B_TILE (16*BPITCH)
#define STAGE_FLOATS (A_TILE + B_TILE)
#define GEMM_SMEM (STAGES*STAGE_FLOATS*4) // 75776 bytes

// Scratch
__device__ float g_qkv[(size_t)ROWS * 768];      // [q(256) | per-head (k32,v32) x8]
__device__ float g_attnout[(size_t)ROWS * Cc];
__device__ float g_pe[T2 * Hh];
__device__ int   g_mask_is_u8;

// ---------------------------------------------------------------------------
__global__ void detect_mask_kernel(const unsigned int* __restrict__ m)
{
    int found = 0;
#pragma unroll
    for (int j = 0; j < 8; j++) {
        if (m[threadIdx.x + j * 256] > 1u) found = 1;
    }
    int any = __syncthreads_or(found);
    if (threadIdx.x == 0) g_mask_is_u8 = any;
}

// ---------------------------------------------------------------------------
__global__ void pe_kernel(const float* __restrict__ pre_table,
                          const float* __restrict__ W_pe,
                          const float* __restrict__ b_pe)
{
    int i = blockIdx.x * blockDim.x + threadIdx.x;
    if (i >= T2 * Hh) return;
    int t = i >> 3;
    int h = i & 7;
    float acc = b_pe[h];
#pragma unroll
    for (int j = 0; j < 5; j++)
        acc += pre_table[t * 5 + j] * W_pe[j * Hh + h];
    g_pe[i] = acc;
}

// ---------------------------------------------------------------------------
__device__ __forceinline__ uint32_t f2tf32(float f)
{
    uint32_t r;
    asm("cvt.rna.tf32.f32 %0, %1;" : "=r"(r) : "f"(f));
    return r;
}

__device__ __forceinline__ void mma_tf32(float* d, const uint32_t* a, const uint32_t* b)
{
    asm volatile(
        "mma.sync.aligned.m16n8k8.row.col.f32.tf32.tf32.f32 "
        "{%0,%1,%2,%3}, {%4,%5,%6,%7}, {%8,%9}, {%0,%1,%2,%3};"
        : "+f"(d[0]), "+f"(d[1]), "+f"(d[2]), "+f"(d[3])
        : "r"(a[0]), "r"(a[1]), "r"(a[2]), "r"(a[3]), "r"(b[0]), "r"(b[1]));
}

__device__ __forceinline__ uint32_t smem_u32(const void* p)
{
    uint32_t r;
    asm("{ .reg .u64 t; cvta.to.shared.u64 t, %1; cvt.u32.u64 %0, t; }"
        : "=r"(r) : "l"(p));
    return r;
}

__device__ __forceinline__ void cp16(uint32_t dst, const void* src)
{
    asm volatile("cp.async.ca.shared.global [%0], [%1], 16;"
                 :: "r"(dst), "l"(src));
}

// ---------------------------------------------------------------------------
// Shared tf32 GEMM body (BM=BN=128, BK=16, 4-stage cp.async pipeline).
// ---------------------------------------------------------------------------
__device__ __forceinline__ void gemm_body(
    const float* __restrict__ A, const float* __restrict__ W,
    const float* __restrict__ bias, float* __restrict__ Cout,
    int K, int Ncols, int ldout, int block_m, int wcol, int outcol,
    float* sm)
{
    const int tid = threadIdx.x;
    const int wid = tid >> 5;
    const int lane = tid & 31;
    const int wm = (wid & 3) * 32;
    const int wn = (wid >> 2) * 64;
    const int lr = lane >> 2;
    const int lc = lane & 3;

    const int arow = tid >> 1;
    const int acol = (tid & 1) * 8;
    const int brow = tid >> 4;
    const int bcol = (tid & 15) * 8;

    const float* Aptr = A + (size_t)(block_m + arow) * K + acol;
    const float* Wptr = W + (size_t)brow * Ncols + wcol + bcol;

    float acc[2][8][4];
#pragma unroll
    for (int i = 0; i < 2; i++)
#pragma unroll
        for (int j = 0; j < 8; j++)
#pragma unroll
            for (int t = 0; t < 4; t++) acc[i][j][t] = 0.f;

    const int NIT = K >> 4;

    auto issue_tile = [&](int s, int k0) {
        float* as = sm + s * STAGE_FLOATS;
        float* bs = as + A_TILE;
        uint32_t ad = smem_u32(as + arow * APITCH + acol);
        const char* asrc = (const char*)(Aptr + k0);
        cp16(ad, asrc);
        cp16(ad + 16, asrc + 16);
        uint32_t bd = smem_u32(bs + brow * BPITCH + bcol);
        const char* bsrc = (const char*)(Wptr + (size_t)k0 * Ncols);
        cp16(bd, bsrc);
        cp16(bd + 16, bsrc + 16);
    };

#pragma unroll
    for (int s = 0; s < STAGES - 1; s++) {
        if (s < NIT) issue_tile(s, s * 16);
        asm volatile("cp.async.commit_group;");
    }

    for (int it = 0; it < NIT; it++) {
        asm volatile("cp.async.wait_group %0;" :: "n"(STAGES - 2));
        __syncthreads();
        if (it + STAGES - 1 < NIT)
            issue_tile((it + STAGES - 1) % STAGES, (it + STAGES - 1) * 16);
        asm volatile("cp.async.commit_group;");

        const float* as = sm + (it % STAGES) * STAGE_FLOATS;
        const float* bs = as + A_TILE;
#pragma unroll
        for (int kk = 0; kk < 16; kk += 8) {
            uint32_t afr[2][4], bfr[8][2];
#pragma unroll
            for (int mf = 0; mf < 2; mf++) {
                const int r = wm + mf * 16 + lr;
                afr[mf][0] = f2tf32(as[r * APITCH + kk + lc]);
                afr[mf][1] = f2tf32(as[(r + 8) * APITCH + kk + lc]);
                afr[mf][2] = f2tf32(as[r * APITCH + kk + lc + 4]);
                afr[mf][3] = f2tf32(as[(r + 8) * APITCH + kk + lc + 4]);
            }
#pragma unroll
            for (int nf = 0; nf < 8; nf++) {
                const int cn = wn + nf * 8 + lr;
                bfr[nf][0] = f2tf32(bs[(kk + lc) * BPITCH + cn]);
                bfr[nf][1] = f2tf32(bs[(kk + lc + 4) * BPITCH + cn]);
            }
#pragma unroll
            for (int mf = 0; mf < 2; mf++)
#pragma unroll
                for (int nf = 0; nf < 8; nf++)
                    mma_tf32(acc[mf][nf], afr[mf], bfr[nf]);
        }
    }

#pragma unroll
    for (int mf = 0; mf < 2; mf++) {
        const int row0 = block_m + wm + mf * 16 + lr;
#pragma unroll
        for (int nf = 0; nf < 8; nf++) {
            const int cl = wn + nf * 8 + lc * 2;
            float2 bv = *(const float2*)(bias + wcol + cl);
            float2 v0 = make_float2(acc[mf][nf][0] + bv.x, acc[mf][nf][1] + bv.y);
            float2 v1 = make_float2(acc[mf][nf][2] + bv.x, acc[mf][nf][3] + bv.y);
            *(float2*)(Cout + (size_t)row0 * ldout + outcol + cl) = v0;
            *(float2*)(Cout + (size_t)(row0 + 8) * ldout + outcol + cl) = v1;
        }
    }
}

// Fused Q+KV projection: grid (6, 64).
__global__ __launch_bounds__(256, 2) void qkv_gemm_kernel(
    const float* __restrict__ A,
    const float* __restrict__ Wq, const float* __restrict__ bq,
    const float* __restrict__ Wkv, const float* __restrict__ bkv,
    float* __restrict__ qkv)
{
    extern __shared__ float sm[];
    const int bx = blockIdx.x;
    const float *W, *bias;
    int Ncols, wcol, outcol;
    if (bx < 2) { W = Wq;  bias = bq;  Ncols = 256; wcol = bx * 128;       outcol = wcol; }
    else        { W = Wkv; bias = bkv; Ncols = 512; wcol = (bx - 2) * 128; outcol = 256 + wcol; }
    gemm_body(A, W, bias, qkv, 256, Ncols, 768, blockIdx.y * 128, wcol, outcol, sm);
}

// Output projection: grid (2, 64).
__global__ __launch_bounds__(256, 2) void proj_gemm_kernel(
    const float* __restrict__ A,
    const float* __restrict__ W, const float* __restrict__ bias,
    float* __restrict__ out)
{
    extern __shared__ float sm[];
    gemm_body(A, W, bias, out, 256, 256, 256,
              blockIdx.y * 128, blockIdx.x * 128, blockIdx.x * 128, sm);
}

// ---------------------------------------------------------------------------
// Fused gather + scores + softmax + weighted-V.
// Broadcast data (member V offsets + softmax weights) staged through smem
// instead of warp shuffles -> ~half the MIO ops of R9.
// ---------------------------------------------------------------------------
__device__ __forceinline__ bool read_mask(const void* cm, int idx, int is_u8)
{
    if (is_u8) return ((const unsigned char*)cm)[idx] != 0;
    return ((const int*)cm)[idx] != 0;
}

__global__ __launch_bounds__(256) void attn_kernel(
    const int* __restrict__ member_idx,
    const void* __restrict__ cluster_mask,
    const int* __restrict__ pe_idx,
    const float* __restrict__ blank_k,
    const float* __restrict__ blank_v)
{
    extern __shared__ float smem[];
    float* kv   = smem;                 // 32 x KP (K only)
    float* qsh  = smem + 32 * KP;       // 256
    float* aw   = qsh + 256;            // 8 heads x 32 weights
    int*   voff = (int*)(aw + 256);     // 32 member V-row offsets

    const int bn   = blockIdx.x;
    const int tid  = threadIdx.x;
    const int h    = tid >> 5;
    const int lane = tid & 31;
    const int b    = bn >> 12;     // N = 4096
    const int is_u8 = g_mask_is_u8;

    // ---- phase 1: stage q + gathered K (cp.async), mask-predicated ----
    const int mbase = bn * Mm;
    const int mrow = tid >> 3;
    const int sub  = tid & 7;
    const bool msk_stage = read_mask(cluster_mask, mbase + mrow, is_u8);

    if (msk_stage) {
        const int gidx = __ldg(member_idx + mbase + mrow);
        const char* src = (const char*)(g_qkv + ((size_t)(b * Nn + gidx)) * 768 + 256);
        uint32_t dst_base = smem_u32(kv + mrow * KP);
#pragma unroll
        for (int j = 0; j < 8; j++) {
            cp16(dst_base + j * 128 + sub * 16, src + j * 256 + sub * 16);
        }
    }
    asm volatile("cp.async.commit_group;");

    qsh[tid] = g_qkv[(size_t)bn * 768 + tid];

    // per-lane member metadata (lane = member m)
    const int  gidx_l = __ldg(member_idx + mbase + lane);
    const bool msk    = read_mask(cluster_mask, mbase + lane, is_u8);
    const int  pid    = pe_idx[mbase + lane];
    const unsigned wmask = __ballot_sync(0xFFFFFFFFu, msk);

    if (tid < 32) voff[tid] = gidx_l * 768;   // warp 0 publishes V-row offsets

    asm volatile("cp.async.wait_group 0;");
    __syncthreads();

    // ---- phase 2: score + softmax (lane = member m) ----
    const float* qh = qsh + h * 32;
    const float4* krow4 = (const float4*)(kv + lane * KP + h * 32);
    float score = 0.f;
#pragma unroll
    for (int i = 0; i < 8; i++) {
        float4 kk = krow4[i];
        score = fmaf(kk.x, qh[4*i+0], score);
        score = fmaf(kk.y, qh[4*i+1], score);
        score = fmaf(kk.z, qh[4*i+2], score);
        score = fmaf(kk.w, qh[4*i+3], score);
    }
    score = score * SCALE + g_pe[pid * Hh + h];
    if (!msk) score = -3.0e38f;   // masked -> exact 0 weight after softmax

    float bsp = qh[lane] * blank_k[h * 32 + lane];
#pragma unroll
    for (int o = 16; o > 0; o >>= 1)
        bsp += __shfl_xor_sync(0xFFFFFFFFu, bsp, o);
    const float bs = bsp * SCALE;

    float mx = score;
#pragma unroll
    for (int o = 16; o > 0; o >>= 1)
        mx = fmaxf(mx, __shfl_xor_sync(0xFFFFFFFFu, mx, o));
    mx = fmaxf(mx, bs);

    float p  = __expf(score - mx);
    float pb = __expf(bs - mx);
    float s = p;
#pragma unroll
    for (int o = 16; o > 0; o >>= 1)
        s += __shfl_xor_sync(0xFFFFFFFFu, s, o);
    s += pb;
    const float inv = 1.f / s;
    const float a  = p * inv;
    const float ab = pb * inv;

    // publish per-head weights to smem (replaces 32 shfl broadcasts)
    aw[h * 32 + lane] = a;
    __syncwarp();

    // ---- phase 3: weighted V sum (lane = channel c) ----
    const float* vb = g_qkv + (size_t)b * Nn * 768 + 256 + h * 64 + 32 + lane;
    float out = ab * blank_v[h * 32 + lane];
    float out2 = 0.f;
#pragma unroll
    for (int c = 0; c < 8; c++) {
        int4   ro = *(const int4*)(voff + c * 4);           // broadcast LDS.128
        float4 wv = *(const float4*)(aw + h * 32 + c * 4);  // broadcast LDS.128
        float v0 = 0.f, v1 = 0.f, v2 = 0.f, v3 = 0.f;
        if ((wmask >> (c * 4 + 0)) & 1u) v0 = __ldg(vb + ro.x);
        if ((wmask >> (c * 4 + 1)) & 1u) v1 = __ldg(vb + ro.y);
        if ((wmask >> (c * 4 + 2)) & 1u) v2 = __ldg(vb + ro.z);
        if ((wmask >> (c * 4 + 3)) & 1u) v3 = __ldg(vb + ro.w);
        out  = fmaf(wv.x, v0, out);
        out2 = fmaf(wv.y, v1, out2);
        out  = fmaf(wv.z, v2, out);
        out2 = fmaf(wv.w, v3, out2);
    }
    out += out2;

    g_attnout[(size_t)bn * Cc + h * 32 + lane] = out;
}

// ---------------------------------------------------------------------------
extern "C" void kernel_launch(void* const* d_in, const int* in_sizes, int n_in,
                              void* d_out, int out_size)
{
    const float* feat   = (const float*)d_in[0];
    const int*   member = (const int*)d_in[1];
    const void*  mask   = d_in[2];
    const int*   peidx  = (const int*)d_in[3];

    int p = 4;
    for (int i = 4; i < n_in; i++) {
        if (in_sizes[i] == 3125) { p = i; break; }
    }
    const float* pre_table = (const float*)d_in[p];
    const float* Wq        = (const float*)d_in[p + 1];
    const float* bq        = (const float*)d_in[p + 2];
    const float* Wkv       = (const float*)d_in[p + 3];
    const float* bkv       = (const float*)d_in[p + 4];
    const float* W_pe      = (const float*)d_in[p + 5];
    const float* b_pe      = (const float*)d_in[p + 6];
    const float* blank_k   = (const float*)d_in[p + 7];
    const float* blank_v   = (const float*)d_in[p + 8];
    const float* Wproj     = (const float*)d_in[p + 9];
    const float* bproj     = (const float*)d_in[p + 10];
    float* out = (float*)d_out;

    float* qkv = nullptr;
    float* attnout = nullptr;
    cudaGetSymbolAddress((void**)&qkv, g_qkv);
    cudaGetSymbolAddress((void**)&attnout, g_attnout);

    cudaFuncSetAttribute(attn_kernel,
                         cudaFuncAttributeMaxDynamicSharedMemorySize, ATTN_SMEM);
    cudaFuncSetAttribute(qkv_gemm_kernel,
                         cudaFuncAttributeMaxDynamicSharedMemorySize, GEMM_SMEM);
    cudaFuncSetAttribute(proj_gemm_kernel,
                         cudaFuncAttributeMaxDynamicSharedMemorySize, GEMM_SMEM);

    detect_mask_kernel<<<1, 256>>>((const unsigned int*)mask);
    pe_kernel<<<(T2 * Hh + 255) / 256, 256>>>(pre_table, W_pe, b_pe);

    {   // fused Q+KV projection
        dim3 grid(6, ROWS / 128);
        qkv_gemm_kernel<<<grid, 256, GEMM_SMEM>>>(feat, Wq, bq, Wkv, bkv, qkv);
    }

    attn_kernel<<<ROWS, 256, ATTN_SMEM>>>(member, mask, peidx, blank_k, blank_v);

    {   // output projection
        dim3 grid(2, ROWS / 128);
        proj_gemm_kernel<<<grid, 256, GEMM_SMEM>>>(attnout, Wproj, bproj, out);
    }
}

// round 11
// speedup vs baseline: 1.1543x; 1.0561x over previous
#include <cuda_runtime.h>
#include <cuda_bf16.h>
#include <math.h>
#include <stdint.h>

// Problem constants
#define Bb 2
#define Nn 4096
#define Mm 32
#define Cc 256
#define Hh 8
#define T2 625
#define SCALE 0.17677669529663687f   // 32^-0.5
#define ROWS (Bb*Nn)                  // 8192

// attn smem: K tile 32x260 + q 256 + weights 256 + voffc 32
#define KP 260
#define ATTN_SMEM ((32*KP + 256 + 256 + 32) * 4) // 35456 bytes

// GEMM pipeline config
#define STAGES 4
#define APITCH 20
#define BPITCH 136
#define A_TILE (128*APITCH)
#define B_TILE (16*BPITCH)
#define STAGE_FLOATS (A_TILE + B_TILE)
#define GEMM_SMEM (STAGES*STAGE_FLOATS*4) // 75776 bytes

// Scratch
__device__ float g_qkv[(size_t)ROWS * 768];      // [q(256) | per-head (k32,v32) x8]
__device__ float g_attnout[(size_t)ROWS * Cc];
__device__ float g_pe[T2 * Hh];
__device__ int   g_mask_is_u8;

// ---------------------------------------------------------------------------
__global__ void detect_mask_kernel(const unsigned int* __restrict__ m)
{
    int found = 0;
#pragma unroll
    for (int j = 0; j < 8; j++) {
        if (m[threadIdx.x + j * 256] > 1u) found = 1;
    }
    int any = __syncthreads_or(found);
    if (threadIdx.x == 0) g_mask_is_u8 = any;
}

// ---------------------------------------------------------------------------
__global__ void pe_kernel(const float* __restrict__ pre_table,
                          const float* __restrict__ W_pe,
                          const float* __restrict__ b_pe)
{
    int i = blockIdx.x * blockDim.x + threadIdx.x;
    if (i >= T2 * Hh) return;
    int t = i >> 3;
    int h = i & 7;
    float acc = b_pe[h];
#pragma unroll
    for (int j = 0; j < 5; j++)
        acc += pre_table[t * 5 + j] * W_pe[j * Hh + h];
    g_pe[i] = acc;
}

// ---------------------------------------------------------------------------
__device__ __forceinline__ uint32_t f2tf32(float f)
{
    uint32_t r;
    asm("cvt.rna.tf32.f32 %0, %1;" : "=r"(r) : "f"(f));
    return r;
}

__device__ __forceinline__ void mma_tf32(float* d, const uint32_t* a, const uint32_t* b)
{
    asm volatile(
        "mma.sync.aligned.m16n8k8.row.col.f32.tf32.tf32.f32 "
        "{%0,%1,%2,%3}, {%4,%5,%6,%7}, {%8,%9}, {%0,%1,%2,%3};"
        : "+f"(d[0]), "+f"(d[1]), "+f"(d[2]), "+f"(d[3])
        : "r"(a[0]), "r"(a[1]), "r"(a[2]), "r"(a[3]), "r"(b[0]), "r"(b[1]));
}

__device__ __forceinline__ uint32_t smem_u32(const void* p)
{
    uint32_t r;
    asm("{ .reg .u64 t; cvta.to.shared.u64 t, %1; cvt.u32.u64 %0, t; }"
        : "=r"(r) : "l"(p));
    return r;
}

__device__ __forceinline__ void cp16(uint32_t dst, const void* src)
{
    asm volatile("cp.async.ca.shared.global [%0], [%1], 16;"
                 :: "r"(dst), "l"(src));
}

// ---------------------------------------------------------------------------
// Shared tf32 GEMM body (BM=BN=128, BK=16, 4-stage cp.async pipeline).
// ---------------------------------------------------------------------------
__device__ __forceinline__ void gemm_body(
    const float* __restrict__ A, const float* __restrict__ W,
    const float* __restrict__ bias, float* __restrict__ Cout,
    int K, int Ncols, int ldout, int block_m, int wcol, int outcol,
    float* sm)
{
    const int tid = threadIdx.x;
    const int wid = tid >> 5;
    const int lane = tid & 31;
    const int wm = (wid & 3) * 32;
    const int wn = (wid >> 2) * 64;
    const int lr = lane >> 2;
    const int lc = lane & 3;

    const int arow = tid >> 1;
    const int acol = (tid & 1) * 8;
    const int brow = tid >> 4;
    const int bcol = (tid & 15) * 8;

    const float* Aptr = A + (size_t)(block_m + arow) * K + acol;
    const float* Wptr = W + (size_t)brow * Ncols + wcol + bcol;

    float acc[2][8][4];
#pragma unroll
    for (int i = 0; i < 2; i++)
#pragma unroll
        for (int j = 0; j < 8; j++)
#pragma unroll
            for (int t = 0; t < 4; t++) acc[i][j][t] = 0.f;

    const int NIT = K >> 4;

    auto issue_tile = [&](int s, int k0) {
        float* as = sm + s * STAGE_FLOATS;
        float* bs = as + A_TILE;
        uint32_t ad = smem_u32(as + arow * APITCH + acol);
        const char* asrc = (const char*)(Aptr + k0);
        cp16(ad, asrc);
        cp16(ad + 16, asrc + 16);
        uint32_t bd = smem_u32(bs + brow * BPITCH + bcol);
        const char* bsrc = (const char*)(Wptr + (size_t)k0 * Ncols);
        cp16(bd, bsrc);
        cp16(bd + 16, bsrc + 16);
    };

#pragma unroll
    for (int s = 0; s < STAGES - 1; s++) {
        if (s < NIT) issue_tile(s, s * 16);
        asm volatile("cp.async.commit_group;");
    }

    for (int it = 0; it < NIT; it++) {
        asm volatile("cp.async.wait_group %0;" :: "n"(STAGES - 2));
        __syncthreads();
        if (it + STAGES - 1 < NIT)
            issue_tile((it + STAGES - 1) % STAGES, (it + STAGES - 1) * 16);
        asm volatile("cp.async.commit_group;");

        const float* as = sm + (it % STAGES) * STAGE_FLOATS;
        const float* bs = as + A_TILE;
#pragma unroll
        for (int kk = 0; kk < 16; kk += 8) {
            uint32_t afr[2][4], bfr[8][2];
#pragma unroll
            for (int mf = 0; mf < 2; mf++) {
                const int r = wm + mf * 16 + lr;
                afr[mf][0] = f2tf32(as[r * APITCH + kk + lc]);
                afr[mf][1] = f2tf32(as[(r + 8) * APITCH + kk + lc]);
                afr[mf][2] = f2tf32(as[r * APITCH + kk + lc + 4]);
                afr[mf][3] = f2tf32(as[(r + 8) * APITCH + kk + lc + 4]);
            }
#pragma unroll
            for (int nf = 0; nf < 8; nf++) {
                const int cn = wn + nf * 8 + lr;
                bfr[nf][0] = f2tf32(bs[(kk + lc) * BPITCH + cn]);
                bfr[nf][1] = f2tf32(bs[(kk + lc + 4) * BPITCH + cn]);
            }
#pragma unroll
            for (int mf = 0; mf < 2; mf++)
#pragma unroll
                for (int nf = 0; nf < 8; nf++)
                    mma_tf32(acc[mf][nf], afr[mf], bfr[nf]);
        }
    }

#pragma unroll
    for (int mf = 0; mf < 2; mf++) {
        const int row0 = block_m + wm + mf * 16 + lr;
#pragma unroll
        for (int nf = 0; nf < 8; nf++) {
            const int cl = wn + nf * 8 + lc * 2;
            float2 bv = *(const float2*)(bias + wcol + cl);
            float2 v0 = make_float2(acc[mf][nf][0] + bv.x, acc[mf][nf][1] + bv.y);
            float2 v1 = make_float2(acc[mf][nf][2] + bv.x, acc[mf][nf][3] + bv.y);
            *(float2*)(Cout + (size_t)row0 * ldout + outcol + cl) = v0;
            *(float2*)(Cout + (size_t)(row0 + 8) * ldout + outcol + cl) = v1;
        }
    }
}

// Fused Q+KV projection: grid (6, 64).
__global__ __launch_bounds__(256, 2) void qkv_gemm_kernel(
    const float* __restrict__ A,
    const float* __restrict__ Wq, const float* __restrict__ bq,
    const float* __restrict__ Wkv, const float* __restrict__ bkv,
    float* __restrict__ qkv)
{
    extern __shared__ float sm[];
    const int bx = blockIdx.x;
    const float *W, *bias;
    int Ncols, wcol, outcol;
    if (bx < 2) { W = Wq;  bias = bq;  Ncols = 256; wcol = bx * 128;       outcol = wcol; }
    else        { W = Wkv; bias = bkv; Ncols = 512; wcol = (bx - 2) * 128; outcol = 256 + wcol; }
    gemm_body(A, W, bias, qkv, 256, Ncols, 768, blockIdx.y * 128, wcol, outcol, sm);
}

// Output projection: grid (2, 64).
__global__ __launch_bounds__(256, 2) void proj_gemm_kernel(
    const float* __restrict__ A,
    const float* __restrict__ W, const float* __restrict__ bias,
    float* __restrict__ out)
{
    extern __shared__ float sm[];
    gemm_body(A, W, bias, out, 256, 256, 256,
              blockIdx.y * 128, blockIdx.x * 128, blockIdx.x * 128, sm);
}

// ---------------------------------------------------------------------------
// Fused gather + scores + softmax + weighted-V with active-member compaction.
// Mask is identical across heads; compact the ~16 active members once per
// block, then phase 3 runs an unpredicated dense loop over the active set.
// ---------------------------------------------------------------------------
__device__ __forceinline__ bool read_mask(const void* cm, int idx, int is_u8)
{
    if (is_u8) return ((const unsigned char*)cm)[idx] != 0;
    return ((const int*)cm)[idx] != 0;
}

__global__ __launch_bounds__(256) void attn_kernel(
    const int* __restrict__ member_idx,
    const void* __restrict__ cluster_mask,
    const int* __restrict__ pe_idx,
    const float* __restrict__ blank_k,
    const float* __restrict__ blank_v)
{
    extern __shared__ float smem[];
    float* kv    = smem;                 // 32 x KP (K only)
    float* qsh   = smem + 32 * KP;       // 256
    float* aw    = qsh + 256;            // 8 heads x 32 compacted weights
    int*   voffc = (int*)(aw + 256);     // 32 compacted V-row offsets

    const int bn   = blockIdx.x;
    const int tid  = threadIdx.x;
    const int h    = tid >> 5;
    const int lane = tid & 31;
    const int b    = bn >> 12;     // N = 4096
    const int is_u8 = g_mask_is_u8;

    // ---- phase 1: stage q + gathered K (cp.async), mask-predicated ----
    const int mbase = bn * Mm;
    const int mrow = tid >> 3;
    const int sub  = tid & 7;
    const bool msk_stage = read_mask(cluster_mask, mbase + mrow, is_u8);

    if (msk_stage) {
        const int gidx = __ldg(member_idx + mbase + mrow);
        const char* src = (const char*)(g_qkv + ((size_t)(b * Nn + gidx)) * 768 + 256);
        uint32_t dst_base = smem_u32(kv + mrow * KP);
#pragma unroll
        for (int j = 0; j < 8; j++) {
            cp16(dst_base + j * 128 + sub * 16, src + j * 256 + sub * 16);
        }
    }
    asm volatile("cp.async.commit_group;");

    qsh[tid] = g_qkv[(size_t)bn * 768 + tid];

    // per-lane member metadata (lane = member m)
    const bool msk = read_mask(cluster_mask, mbase + lane, is_u8);
    const unsigned wmask = __ballot_sync(0xFFFFFFFFu, msk);
    const int n_act = __popc(wmask);
    const int n4 = (n_act + 3) & ~3;
    const int pos = __popc(wmask & ((1u << lane) - 1u));

    // warp 0 publishes compacted V-row offsets (+ zero padding to n4)
    if (tid < 32) {
        if (msk) {
            const int gidx_l = __ldg(member_idx + mbase + lane);
            voffc[pos] = gidx_l * 768;
        }
        if (lane >= n_act && lane < n4) voffc[lane] = 0;
    }

    asm volatile("cp.async.wait_group 0;");
    __syncthreads();

    // ---- phase 2: score + softmax (lane = member m) ----
    const float* qh = qsh + h * 32;
    float score = -3.0e38f;
    if (msk) {
        const float4* krow4 = (const float4*)(kv + lane * KP + h * 32);
        float sc = 0.f;
#pragma unroll
        for (int i = 0; i < 8; i++) {
            float4 kk = krow4[i];
            sc = fmaf(kk.x, qh[4*i+0], sc);
            sc = fmaf(kk.y, qh[4*i+1], sc);
            sc = fmaf(kk.z, qh[4*i+2], sc);
            sc = fmaf(kk.w, qh[4*i+3], sc);
        }
        const int pid = pe_idx[mbase + lane];
        score = sc * SCALE + g_pe[pid * Hh + h];
    }

    float bsp = qh[lane] * blank_k[h * 32 + lane];
#pragma unroll
    for (int o = 16; o > 0; o >>= 1)
        bsp += __shfl_xor_sync(0xFFFFFFFFu, bsp, o);
    const float bs = bsp * SCALE;

    float mx = score;
#pragma unroll
    for (int o = 16; o > 0; o >>= 1)
        mx = fmaxf(mx, __shfl_xor_sync(0xFFFFFFFFu, mx, o));
    mx = fmaxf(mx, bs);

    float p  = __expf(score - mx);
    float pb = __expf(bs - mx);
    float s = p;
#pragma unroll
    for (int o = 16; o > 0; o >>= 1)
        s += __shfl_xor_sync(0xFFFFFFFFu, s, o);
    s += pb;
    const float inv = 1.f / s;
    const float a  = p * inv;
    const float ab = pb * inv;

    // publish per-head weights compacted (+ zero padding), warp-local
    if (msk) aw[h * 32 + pos] = a;
    if (lane >= n_act && lane < n4) aw[h * 32 + lane] = 0.f;
    __syncwarp();

    // ---- phase 3: dense weighted V sum over active members (lane = channel) ----
    const float* vb = g_qkv + (size_t)b * Nn * 768 + 256 + h * 64 + 32 + lane;
    float out = ab * blank_v[h * 32 + lane];
    float out2 = 0.f;
    for (int c = 0; c < n4; c += 4) {
        int4   ro = *(const int4*)(voffc + c);         // broadcast LDS.128
        float4 wv = *(const float4*)(aw + h * 32 + c); // broadcast LDS.128
        float v0 = __ldg(vb + ro.x);
        float v1 = __ldg(vb + ro.y);
        float v2 = __ldg(vb + ro.z);
        float v3 = __ldg(vb + ro.w);
        out  = fmaf(wv.x, v0, out);
        out2 = fmaf(wv.y, v1, out2);
        out  = fmaf(wv.z, v2, out);
        out2 = fmaf(wv.w, v3, out2);
    }
    out += out2;

    g_attnout[(size_t)bn * Cc + h * 32 + lane] = out;
}

// ---------------------------------------------------------------------------
extern "C" void kernel_launch(void* const* d_in, const int* in_sizes, int n_in,
                              void* d_out, int out_size)
{
    const float* feat   = (const float*)d_in[0];
    const int*   member = (const int*)d_in[1];
    const void*  mask   = d_in[2];
    const int*   peidx  = (const int*)d_in[3];

    int p = 4;
    for (int i = 4; i < n_in; i++) {
        if (in_sizes[i] == 3125) { p = i; break; }
    }
    const float* pre_table = (const float*)d_in[p];
    const float* Wq        = (const float*)d_in[p + 1];
    const float* bq        = (const float*)d_in[p + 2];
    const float* Wkv       = (const float*)d_in[p + 3];
    const float* bkv       = (const float*)d_in[p + 4];
    const float* W_pe      = (const float*)d_in[p + 5];
    const float* b_pe      = (const float*)d_in[p + 6];
    const float* blank_k   = (const float*)d_in[p + 7];
    const float* blank_v   = (const float*)d_in[p + 8];
    const float* Wproj     = (const float*)d_in[p + 9];
    const float* bproj     = (const float*)d_in[p + 10];
    float* out = (float*)d_out;

    float* qkv = nullptr;
    float* attnout = nullptr;
    cudaGetSymbolAddress((void**)&qkv, g_qkv);
    cudaGetSymbolAddress((void**)&attnout, g_attnout);

    cudaFuncSetAttribute(attn_kernel,
                         cudaFuncAttributeMaxDynamicSharedMemorySize, ATTN_SMEM);
    cudaFuncSetAttribute(qkv_gemm_kernel,
                         cudaFuncAttributeMaxDynamicSharedMemorySize, GEMM_SMEM);
    cudaFuncSetAttribute(proj_gemm_kernel,
                         cudaFuncAttributeMaxDynamicSharedMemorySize, GEMM_SMEM);

    detect_mask_kernel<<<1, 256>>>((const unsigned int*)mask);
    pe_kernel<<<(T2 * Hh + 255) / 256, 256>>>(pre_table, W_pe, b_pe);

    {   // fused Q+KV projection
        dim3 grid(6, ROWS / 128);
        qkv_gemm_kernel<<<grid, 256, GEMM_SMEM>>>(feat, Wq, bq, Wkv, bkv, qkv);
    }

    attn_kernel<<<ROWS, 256, ATTN_SMEM>>>(member, mask, peidx, blank_k, blank_v);

    {   // output projection
        dim3 grid(2, ROWS / 128);
        proj_gemm_kernel<<<grid, 256, GEMM_SMEM>>>(attnout, Wproj, bproj, out);
    }
}